// round 1
// baseline (speedup 1.0000x reference)
#include <cuda_runtime.h>

#define F       128
#define NB      3
#define P       32      // points per block
#define PH      16      // points per point-group (2 groups of 128 threads)
#define THREADS 256
#define OMEGA   30.0f
#define WS      129     // padded stride for transposed weights (conflict-free)

// Stage W (row-major [F][F], z[j] = sum_i W[j][i]*x[i]) transposed into shared:
// Wt[i*WS + j] = W[j*F + i]
__device__ __forceinline__ void stage_weights(const float* __restrict__ gw,
                                              float* __restrict__ Wt) {
    for (int t = threadIdx.x; t < (F * F) / 4; t += THREADS) {
        int j  = t >> 5;            // row (feature j), F/4 = 32 float4 per row
        int i4 = (t & 31) << 2;     // starting i
        float4 v = __ldg(reinterpret_cast<const float4*>(gw + j * F + i4));
        Wt[(i4 + 0) * WS + j] = v.x;
        Wt[(i4 + 1) * WS + j] = v.y;
        Wt[(i4 + 2) * WS + j] = v.z;
        Wt[(i4 + 3) * WS + j] = v.w;
    }
}

// acc[v][p] = sum_i Wt[i][j] * X[(v*P + pbase + p)*F + i]
__device__ __forceinline__ void matmul(const float* __restrict__ Wt,
                                       const float* __restrict__ X,
                                       int j, int pbase, float acc[4][PH]) {
#pragma unroll
    for (int v = 0; v < 4; v++)
#pragma unroll
        for (int p = 0; p < PH; p++) acc[v][p] = 0.0f;

    const float* Xb = X + pbase * F;   // offsets below are compile-time constants

#pragma unroll 2
    for (int i = 0; i < F; i += 4) {
        float w0 = Wt[(i + 0) * WS + j];
        float w1 = Wt[(i + 1) * WS + j];
        float w2 = Wt[(i + 2) * WS + j];
        float w3 = Wt[(i + 3) * WS + j];
#pragma unroll
        for (int v = 0; v < 4; v++) {
#pragma unroll
            for (int p = 0; p < PH; p++) {
                const float4 x =
                    *reinterpret_cast<const float4*>(Xb + (v * P + p) * F + i);
                float a = acc[v][p];
                a = fmaf(w0, x.x, a);
                a = fmaf(w1, x.y, a);
                a = fmaf(w2, x.z, a);
                a = fmaf(w3, x.w, a);
                acc[v][p] = a;
            }
        }
    }
}

__global__ void __launch_bounds__(THREADS, 1)
fsrn_kernel(const float* __restrict__ coords,
            const float* __restrict__ first_w, const float* __restrict__ first_b,
            const float* __restrict__ res_w1,  const float* __restrict__ res_b1,
            const float* __restrict__ res_w2,  const float* __restrict__ res_b2,
            const float* __restrict__ final_w,
            float* __restrict__ out) {
    extern __shared__ float smem[];
    float* Wt  = smem;                 // WS*F
    float* S   = Wt + WS * F;          // 4*P*F : rows [v=0 primal, v=1..3 tangents]
    float* Bb  = S + 4 * P * F;        // 4*P*F : intermediate s1/ds1
    float* Jsh = Bb + 4 * P * F;       // P*12

    const int tid   = threadIdx.x;
    const int j     = tid & (F - 1);
    const int pg    = tid >> 7;
    const int pbase = pg * PH;
    const int blockBase = blockIdx.x * P;

    // ---- first layer: z0 = fw @ c + fb ; h = sin(Wz0); dh_k = W cos(Wz0) * fw[:,k]
    {
        const float fw0 = first_w[j * 3 + 0];
        const float fw1 = first_w[j * 3 + 1];
        const float fw2 = first_w[j * 3 + 2];
        const float fb  = first_b[j];
#pragma unroll
        for (int p = 0; p < PH; p++) {
            int n_idx = blockBase + pbase + p;
            float cx = __ldg(coords + n_idx * 3 + 0);
            float cy = __ldg(coords + n_idx * 3 + 1);
            float cz = __ldg(coords + n_idx * 3 + 2);
            float z = fmaf(fw0, cx, fmaf(fw1, cy, fmaf(fw2, cz, fb)));
            float sn, cs;
            __sincosf(OMEGA * z, &sn, &cs);
            float c0 = OMEGA * cs;
            S[(0 * P + pbase + p) * F + j] = sn;
            S[(1 * P + pbase + p) * F + j] = c0 * fw0;
            S[(2 * P + pbase + p) * F + j] = c0 * fw1;
            S[(3 * P + pbase + p) * F + j] = c0 * fw2;
        }
    }
    __syncthreads();

    // ---- residual blocks
    float acc[4][PH];
    for (int b = 0; b < NB; b++) {
        const float s = (b == 0) ? 1.0f : 0.5f;

        stage_weights(res_w1 + b * F * F, Wt);
        __syncthreads();
        matmul(Wt, S, j, pbase, acc);
        {
            const float b1 = res_b1[b * F + j];
#pragma unroll
            for (int p = 0; p < PH; p++) {
                float z = fmaf(s, acc[0][p], b1);
                float sn, cs;
                __sincosf(OMEGA * z, &sn, &cs);
                float c = OMEGA * cs * s;
                Bb[(0 * P + pbase + p) * F + j] = sn;
                Bb[(1 * P + pbase + p) * F + j] = c * acc[1][p];
                Bb[(2 * P + pbase + p) * F + j] = c * acc[2][p];
                Bb[(3 * P + pbase + p) * F + j] = c * acc[3][p];
            }
        }
        __syncthreads();

        stage_weights(res_w2 + b * F * F, Wt);
        __syncthreads();
        matmul(Wt, Bb, j, pbase, acc);
        {
            const float b2 = res_b2[b * F + j];
#pragma unroll
            for (int p = 0; p < PH; p++) {
                float z = acc[0][p] + b2;
                float sn, cs;
                __sincosf(OMEGA * z, &sn, &cs);
                float c = OMEGA * cs;
                S[(0 * P + pbase + p) * F + j] += sn;
                S[(1 * P + pbase + p) * F + j] += c * acc[1][p];
                S[(2 * P + pbase + p) * F + j] += c * acc[2][p];
                S[(3 * P + pbase + p) * F + j] += c * acc[3][p];
            }
        }
        __syncthreads();
    }

    // ---- final layer jacobian entries: J[p][jo][k] = final_w[jo,:] . dh_k[p]
    {
        const int warp = tid >> 5;
        const int lane = tid & 31;
        for (int t = warp; t < P * 12; t += (THREADS / 32)) {
            int p   = t / 12;
            int rem = t - p * 12;       // rem = jo*3 + k
            int jo  = rem / 3;
            int k   = rem - jo * 3;
            const float* fw = final_w + jo * F;
            const float* sv = S + ((k + 1) * P + p) * F;
            float partial = 0.0f;
#pragma unroll
            for (int q = 0; q < 4; q++)
                partial = fmaf(__ldg(fw + lane + 32 * q), sv[lane + 32 * q], partial);
#pragma unroll
            for (int off = 16; off; off >>= 1)
                partial += __shfl_down_sync(0xffffffffu, partial, off);
            if (lane == 0) Jsh[p * 12 + rem] = partial;
        }
    }
    __syncthreads();

    // ---- combine rotation-free + divergence-free and write out
    if (tid < P) {
        const float* Jp = Jsh + tid * 12;   // index jo*3 + k
        int n_idx = blockBase + tid;
        float o0 = Jp[0 * 3 + 0] + Jp[3 * 3 + 1] - Jp[2 * 3 + 2];
        float o1 = Jp[0 * 3 + 1] + Jp[1 * 3 + 2] - Jp[3 * 3 + 0];
        float o2 = Jp[0 * 3 + 2] + Jp[2 * 3 + 0] - Jp[1 * 3 + 1];
        out[n_idx * 3 + 0] = o0;
        out[n_idx * 3 + 1] = o1;
        out[n_idx * 3 + 2] = o2;
    }
}

extern "C" void kernel_launch(void* const* d_in, const int* in_sizes, int n_in,
                              void* d_out, int out_size) {
    const float* coords  = (const float*)d_in[0];
    const float* first_w = (const float*)d_in[1];
    const float* first_b = (const float*)d_in[2];
    const float* res_w1  = (const float*)d_in[3];
    const float* res_b1  = (const float*)d_in[4];
    const float* res_w2  = (const float*)d_in[5];
    const float* res_b2  = (const float*)d_in[6];
    const float* final_w = (const float*)d_in[7];
    // final_b (d_in[8]) drops out of the jacobian — unused.

    int n = in_sizes[0] / 3;
    int smem_bytes = (WS * F + 8 * P * F + P * 12) * (int)sizeof(float);

    cudaFuncSetAttribute(fsrn_kernel,
                         cudaFuncAttributeMaxDynamicSharedMemorySize, smem_bytes);

    fsrn_kernel<<<n / P, THREADS, smem_bytes>>>(
        coords, first_w, first_b, res_w1, res_b1, res_w2, res_b2,
        final_w, (float*)d_out);
}

// round 2
// speedup vs baseline: 1.8412x; 1.8412x over previous
#include <cuda_runtime.h>

typedef unsigned long long ull;

#define F       128
#define NB      3
#define P       32      // points per block
#define THREADS 256
#define OMEGA   30.0f

// Pre-transposed + permuted weights: g_wt[layer][i*F + perm(j)] = W[j][i]
// layer = b*2 + (0:w1, 1:w2). perm(j) groups j so that thread jg's 8 features
// load as two conflict-free float4s at words jg*4 and 64+jg*4.
__device__ __align__(16) float g_wt[6 * F * F];

__device__ __forceinline__ int perm_j(int j) {
    return ((j & 4) << 4) | ((j >> 3) << 2) | (j & 3);
}

__device__ __forceinline__ ull dup2(float w) {
    ull r; asm("mov.b64 %0, {%1, %1};" : "=l"(r) : "f"(w)); return r;
}
__device__ __forceinline__ float2 unpack2(ull v) {
    float2 r; asm("mov.b64 {%0, %1}, %2;" : "=f"(r.x), "=f"(r.y) : "l"(v)); return r;
}
__device__ __forceinline__ ull ffma2(ull a, ull b, ull c) {
    ull d; asm("fma.rn.f32x2 %0, %1, %2, %3;" : "=l"(d) : "l"(a), "l"(b), "l"(c)); return d;
}

// ---------------- weight transpose pre-kernel ----------------
__global__ void transpose_weights_kernel(const float* __restrict__ res_w1,
                                         const float* __restrict__ res_w2) {
    int t = blockIdx.x * blockDim.x + threadIdx.x;
    if (t >= 6 * F * F) return;
    int layer = t >> 14;            // / (F*F)
    int e     = t & (F * F - 1);
    int j     = e >> 7;
    int i     = e & (F - 1);        // consecutive t -> consecutive i (coalesced read)
    int b     = layer >> 1;
    const float* src = (layer & 1) ? (res_w2 + b * F * F) : (res_w1 + b * F * F);
    g_wt[layer * F * F + i * F + perm_j(j)] = src[j * F + i];
}

// ---------------- main kernel helpers ----------------

// Copy one pre-transposed weight matrix (64KB) into shared. Coalesced, conflict-free.
__device__ __forceinline__ void stage(const float* __restrict__ gsrc,
                                      float* __restrict__ Wsm, int tid) {
    const float4* s4 = reinterpret_cast<const float4*>(gsrc);
    float4* d4 = reinterpret_cast<float4*>(Wsm);
#pragma unroll
    for (int t = tid; t < (F * F) / 4; t += THREADS)
        d4[t] = __ldg(s4 + t);
}

// acc[c][v] (float2 over 2 points) = sum_i W[j=8*jg+c][i] * X[v][i][2*pg + {0,1}]
// X2 layout: float2 row (v*F + i) has 16 float2 entries, swizzled: entry
// (p-pair q) stored at q ^ ((i>>3)&15).
__device__ __forceinline__ void matmul(const float* __restrict__ Wsm,
                                       const float2* __restrict__ X2,
                                       int jg, int pg, ull acc[8][4]) {
#pragma unroll
    for (int c = 0; c < 8; c++)
#pragma unroll
        for (int v = 0; v < 4; v++) acc[c][v] = 0ull;

    const float* wp = Wsm + jg * 4;
#pragma unroll 4
    for (int i = 0; i < F; i++) {
        const float4 wa = *reinterpret_cast<const float4*>(wp + i * F);
        const float4 wb = *reinterpret_cast<const float4*>(wp + i * F + 64);
        const int xoff = i * 16 + (pg ^ ((i >> 3) & 15));
        const ull x0 = *reinterpret_cast<const ull*>(X2 + xoff);
        const ull x1 = *reinterpret_cast<const ull*>(X2 + 2048 + xoff);
        const ull x2 = *reinterpret_cast<const ull*>(X2 + 4096 + xoff);
        const ull x3 = *reinterpret_cast<const ull*>(X2 + 6144 + xoff);
        ull w;
        w = dup2(wa.x);
        acc[0][0] = ffma2(w, x0, acc[0][0]); acc[0][1] = ffma2(w, x1, acc[0][1]);
        acc[0][2] = ffma2(w, x2, acc[0][2]); acc[0][3] = ffma2(w, x3, acc[0][3]);
        w = dup2(wa.y);
        acc[1][0] = ffma2(w, x0, acc[1][0]); acc[1][1] = ffma2(w, x1, acc[1][1]);
        acc[1][2] = ffma2(w, x2, acc[1][2]); acc[1][3] = ffma2(w, x3, acc[1][3]);
        w = dup2(wa.z);
        acc[2][0] = ffma2(w, x0, acc[2][0]); acc[2][1] = ffma2(w, x1, acc[2][1]);
        acc[2][2] = ffma2(w, x2, acc[2][2]); acc[2][3] = ffma2(w, x3, acc[2][3]);
        w = dup2(wa.w);
        acc[3][0] = ffma2(w, x0, acc[3][0]); acc[3][1] = ffma2(w, x1, acc[3][1]);
        acc[3][2] = ffma2(w, x2, acc[3][2]); acc[3][3] = ffma2(w, x3, acc[3][3]);
        w = dup2(wb.x);
        acc[4][0] = ffma2(w, x0, acc[4][0]); acc[4][1] = ffma2(w, x1, acc[4][1]);
        acc[4][2] = ffma2(w, x2, acc[4][2]); acc[4][3] = ffma2(w, x3, acc[4][3]);
        w = dup2(wb.y);
        acc[5][0] = ffma2(w, x0, acc[5][0]); acc[5][1] = ffma2(w, x1, acc[5][1]);
        acc[5][2] = ffma2(w, x2, acc[5][2]); acc[5][3] = ffma2(w, x3, acc[5][3]);
        w = dup2(wb.z);
        acc[6][0] = ffma2(w, x0, acc[6][0]); acc[6][1] = ffma2(w, x1, acc[6][1]);
        acc[6][2] = ffma2(w, x2, acc[6][2]); acc[6][3] = ffma2(w, x3, acc[6][3]);
        w = dup2(wb.w);
        acc[7][0] = ffma2(w, x0, acc[7][0]); acc[7][1] = ffma2(w, x1, acc[7][1]);
        acc[7][2] = ffma2(w, x2, acc[7][2]); acc[7][3] = ffma2(w, x3, acc[7][3]);
    }
}

__global__ void __launch_bounds__(THREADS, 1)
fsrn_kernel(const float* __restrict__ coords,
            const float* __restrict__ first_w, const float* __restrict__ first_b,
            const float* __restrict__ res_b1,  const float* __restrict__ res_b2,
            const float* __restrict__ final_w,
            float* __restrict__ out) {
    extern __shared__ float smem[];
    float*  Wsm = smem;                               // F*F floats (64KB)
    float2* S2  = reinterpret_cast<float2*>(smem + F * F);   // 4*F rows x 16 float2
    float2* B2  = S2 + 4 * F * 16;                            // same size

    const int tid = threadIdx.x;
    const int jg  = tid & 15;       // 16 feature groups, Jt=8 features each
    const int pg  = tid >> 4;       // 16 point-pair groups, Pt=2 points each
    const int po  = pg ^ jg;        // swizzled float2 offset for rows j in this jg
    const int blockBase = blockIdx.x * P;

    // ---- first layer: h = sin(omega*(fw@c + fb)); dh_k = omega*cos(..)*fw[:,k]
    {
        const int p0 = (blockBase + 2 * pg) * 3;
        const float c0x = __ldg(coords + p0 + 0);
        const float c0y = __ldg(coords + p0 + 1);
        const float c0z = __ldg(coords + p0 + 2);
        const float c1x = __ldg(coords + p0 + 3);
        const float c1y = __ldg(coords + p0 + 4);
        const float c1z = __ldg(coords + p0 + 5);
#pragma unroll
        for (int c = 0; c < 8; c++) {
            const int j = jg * 8 + c;
            const float f0 = __ldg(first_w + j * 3 + 0);
            const float f1 = __ldg(first_w + j * 3 + 1);
            const float f2 = __ldg(first_w + j * 3 + 2);
            const float fb = __ldg(first_b + j);
            float za = fmaf(f0, c0x, fmaf(f1, c0y, fmaf(f2, c0z, fb)));
            float zb = fmaf(f0, c1x, fmaf(f1, c1y, fmaf(f2, c1z, fb)));
            float sa, ca, sb, cb;
            __sincosf(OMEGA * za, &sa, &ca);
            __sincosf(OMEGA * zb, &sb, &cb);
            float ga = OMEGA * ca, gb = OMEGA * cb;
            S2[(0 * F + j) * 16 + po] = make_float2(sa, sb);
            S2[(1 * F + j) * 16 + po] = make_float2(ga * f0, gb * f0);
            S2[(2 * F + j) * 16 + po] = make_float2(ga * f1, gb * f1);
            S2[(3 * F + j) * 16 + po] = make_float2(ga * f2, gb * f2);
        }
    }

    // ---- residual blocks
    ull acc[8][4];
    for (int b = 0; b < NB; b++) {
        const float s = (b == 0) ? 1.0f : 0.5f;

        __syncthreads();                       // S2 writes visible; Wsm free
        stage(g_wt + (2 * b) * F * F, Wsm, tid);
        __syncthreads();

        matmul(Wsm, S2, jg, pg, acc);
        // epilogue 1: B = sin(omega*(s*z+b1)); dB = omega*cos*s*dz
#pragma unroll
        for (int c = 0; c < 8; c++) {
            const int j = jg * 8 + c;
            const float b1 = __ldg(res_b1 + b * F + j);
            float2 z = unpack2(acc[c][0]);
            float sa, ca, sb, cb;
            __sincosf(OMEGA * fmaf(s, z.x, b1), &sa, &ca);
            __sincosf(OMEGA * fmaf(s, z.y, b1), &sb, &cb);
            const float ga = OMEGA * s * ca, gb = OMEGA * s * cb;
            B2[(0 * F + j) * 16 + po] = make_float2(sa, sb);
#pragma unroll
            for (int v = 1; v < 4; v++) {
                float2 d = unpack2(acc[c][v]);
                B2[(v * F + j) * 16 + po] = make_float2(ga * d.x, gb * d.y);
            }
        }
        __syncthreads();                       // B2 done; Wsm free
        stage(g_wt + (2 * b + 1) * F * F, Wsm, tid);
        __syncthreads();

        matmul(Wsm, B2, jg, pg, acc);
        // epilogue 2: S += sin(omega*(z+b2)); dS += omega*cos*dz
#pragma unroll
        for (int c = 0; c < 8; c++) {
            const int j = jg * 8 + c;
            const float b2 = __ldg(res_b2 + b * F + j);
            float2 z = unpack2(acc[c][0]);
            float sa, ca, sb, cb;
            __sincosf(OMEGA * (z.x + b2), &sa, &ca);
            __sincosf(OMEGA * (z.y + b2), &sb, &cb);
            const float ga = OMEGA * ca, gb = OMEGA * cb;
            {
                const int idx = (0 * F + j) * 16 + po;
                float2 o = S2[idx];
                S2[idx] = make_float2(o.x + sa, o.y + sb);
            }
#pragma unroll
            for (int v = 1; v < 4; v++) {
                const int idx = (v * F + j) * 16 + po;
                float2 d = unpack2(acc[c][v]);
                float2 o = S2[idx];
                S2[idx] = make_float2(fmaf(ga, d.x, o.x), fmaf(gb, d.y, o.y));
            }
        }
    }
    __syncthreads();

    // ---- final layer: J[p][jo][k] = final_w[jo,:] . dh_k[p]
    // Thread (jg,pg) accumulates over its i-slice [8*jg, 8*jg+8), then a
    // half-warp (width-16) shuffle reduction combines the 16 jg partials.
    ull part[4][3];
#pragma unroll
    for (int jo = 0; jo < 4; jo++)
#pragma unroll
        for (int k = 0; k < 3; k++) part[jo][k] = 0ull;

#pragma unroll
    for (int ii = 0; ii < 8; ii++) {
        const int i = jg * 8 + ii;           // (i>>3)&15 == jg -> offset po
        ull xk0 = *reinterpret_cast<const ull*>(S2 + (1 * F + i) * 16 + po);
        ull xk1 = *reinterpret_cast<const ull*>(S2 + (2 * F + i) * 16 + po);
        ull xk2 = *reinterpret_cast<const ull*>(S2 + (3 * F + i) * 16 + po);
#pragma unroll
        for (int jo = 0; jo < 4; jo++) {
            ull fw = dup2(__ldg(final_w + jo * F + i));
            part[jo][0] = ffma2(fw, xk0, part[jo][0]);
            part[jo][1] = ffma2(fw, xk1, part[jo][1]);
            part[jo][2] = ffma2(fw, xk2, part[jo][2]);
        }
    }
    float2 J[4][3];
#pragma unroll
    for (int jo = 0; jo < 4; jo++)
#pragma unroll
        for (int k = 0; k < 3; k++) J[jo][k] = unpack2(part[jo][k]);

#pragma unroll
    for (int off = 8; off; off >>= 1) {
#pragma unroll
        for (int jo = 0; jo < 4; jo++)
#pragma unroll
            for (int k = 0; k < 3; k++) {
                J[jo][k].x += __shfl_down_sync(0xffffffffu, J[jo][k].x, off, 16);
                J[jo][k].y += __shfl_down_sync(0xffffffffu, J[jo][k].y, off, 16);
            }
    }

    if (jg == 0) {
        const int p0 = blockBase + 2 * pg;
        float o0x = J[0][0].x + J[3][1].x - J[2][2].x;
        float o1x = J[0][1].x + J[1][2].x - J[3][0].x;
        float o2x = J[0][2].x + J[2][0].x - J[1][1].x;
        float o0y = J[0][0].y + J[3][1].y - J[2][2].y;
        float o1y = J[0][1].y + J[1][2].y - J[3][0].y;
        float o2y = J[0][2].y + J[2][0].y - J[1][1].y;
        out[p0 * 3 + 0] = o0x;
        out[p0 * 3 + 1] = o1x;
        out[p0 * 3 + 2] = o2x;
        out[p0 * 3 + 3] = o0y;
        out[p0 * 3 + 4] = o1y;
        out[p0 * 3 + 5] = o2y;
    }
}

extern "C" void kernel_launch(void* const* d_in, const int* in_sizes, int n_in,
                              void* d_out, int out_size) {
    const float* coords  = (const float*)d_in[0];
    const float* first_w = (const float*)d_in[1];
    const float* first_b = (const float*)d_in[2];
    const float* res_w1  = (const float*)d_in[3];
    const float* res_b1  = (const float*)d_in[4];
    const float* res_w2  = (const float*)d_in[5];
    const float* res_b2  = (const float*)d_in[6];
    const float* final_w = (const float*)d_in[7];
    // final_b (d_in[8]) drops out of the jacobian — unused.

    int n = in_sizes[0] / 3;

    transpose_weights_kernel<<<(6 * F * F + 255) / 256, 256>>>(res_w1, res_w2);

    int smem_bytes = 3 * F * F * (int)sizeof(float);   // 192KB: W + S + B
    cudaFuncSetAttribute(fsrn_kernel,
                         cudaFuncAttributeMaxDynamicSharedMemorySize, smem_bytes);
    fsrn_kernel<<<n / P, THREADS, smem_bytes>>>(
        coords, first_w, first_b, res_b1, res_b2, final_w, (float*)d_out);
}